// round 14
// baseline (speedup 1.0000x reference)
#include <cuda_runtime.h>
#include <cuda_fp16.h>
#include <cstdint>
#include <cstddef>

#define B_SZ 1024
#define T_SZ 128
#define M_SZ 256
#define P_SZ 256
#define TS   127   // T-1 recurrence steps
#define NBLK 512   // persistent grid (co-resident: 4/SM * 148 = 592 >= 512)

// ---------------- scratch (static device globals) ---------------------------
// interleaved per-(b,t) row: [ A[0..255] | X[0..255] ] fp16, stride 512
__device__ __half g_AX[(size_t)B_SZ * T_SZ * 512];
__device__ __half g_HCh[B_SZ * 512];                 // fp16 mirror of [h|c]
__device__ __half g_Wdd16[256 * 512];                // WU_d[:, :512] fp16
__device__ __half g_Whh16[1024 * 256];               // W_hh fp16
__device__ __half g_Wdx16[256 * 256];                // WU_d[:, 512:768] fp16
__device__ float  g_bias[4 * P_SZ];                  // b_ih + b_hh
__device__ __half g_U1h[B_SZ * M_SZ];                // d-part preact, K 0:256 (fp16)
__device__ __half g_U2h[B_SZ * M_SZ];                // d-part preact, K 256:512 (fp16)
__device__ __half g_GATESh[B_SZ * 4 * P_SZ];         // h @ W_hh^T (fp16)
__device__ float  g_HC[B_SZ * 512];                  // fp32 master [h|c]
__device__ float  g_CTX[B_SZ * M_SZ];                // attention context (last step)

// grid barrier state
__device__ unsigned g_bar_count = 0;
__device__ unsigned g_bar_gen   = 0;

// ---------------- init ------------------------------------------------------
__global__ void init_hc_kernel() {
    int i = blockIdx.x * blockDim.x + threadIdx.x;
    if (i < B_SZ * 512) { g_HC[i] = 0.0f; g_HCh[i] = __float2half_rn(0.0f); }
}

// ---------------- X (t,b,m) fp32 -> g_AX[b,t, 256+m] fp16 -------------------
__global__ void convert_x_kernel(const float* __restrict__ X) {
    int row = blockIdx.x * 4 + (threadIdx.x >> 6);   // row = t*B + b
    int c4  = (threadIdx.x & 63) * 4;
    int t = row >> 10;
    int b = row & 1023;
    float4 v = __ldg((const float4*)(X + (size_t)row * M_SZ + c4));
    __half2* dst = (__half2*)(g_AX + ((size_t)(b << 7) + t) * 512 + 256 + c4);
    dst[0] = __floats2half2_rn(v.x, v.y);
    dst[1] = __floats2half2_rn(v.z, v.w);
}

// ---------------- weights -> fp16, fused bias -------------------------------
__global__ void convert_w_kernel(const float* __restrict__ WU_d,
                                 const float* __restrict__ W_hh,
                                 const float* __restrict__ b_ih,
                                 const float* __restrict__ b_hh) {
    int i = blockIdx.x * 256 + threadIdx.x;          // 0 .. 262143
    if (i < 256 * 512) {
        int r = i >> 9, k = i & 511;
        g_Wdd16[i] = __float2half_rn(WU_d[r * 768 + k]);
    }
    if (i < 256 * 256) {
        int r = i >> 8, k = i & 255;
        g_Wdx16[i] = __float2half_rn(WU_d[r * 768 + 512 + k]);
    }
    if (i < 1024 * 256) {
        g_Whh16[i] = __float2half_rn(W_hh[i]);
    }
    if (i < 1024) {
        g_bias[i] = b_ih[i] + b_hh[i];
    }
}

// ---------------- HMMA helpers ----------------------------------------------
__device__ __forceinline__ void ldsm4(uint32_t* r, uint32_t addr) {
    asm volatile("ldmatrix.sync.aligned.m8n8.x4.shared.b16 {%0,%1,%2,%3}, [%4];"
                 : "=r"(r[0]), "=r"(r[1]), "=r"(r[2]), "=r"(r[3]) : "r"(addr));
}

__device__ __forceinline__ void mma_16816(float* acc, const uint32_t* a,
                                          uint32_t b0, uint32_t b1) {
    asm volatile(
        "mma.sync.aligned.m16n8k16.row.col.f32.f16.f16.f32 "
        "{%0,%1,%2,%3},{%4,%5,%6,%7},{%8,%9},{%0,%1,%2,%3};"
        : "+f"(acc[0]), "+f"(acc[1]), "+f"(acc[2]), "+f"(acc[3])
        : "r"(a[0]), "r"(a[1]), "r"(a[2]), "r"(a[3]), "r"(b0), "r"(b1));
}

__device__ __forceinline__ __half2 h2tanh_fast(__half2 x) {
    uint32_t xi = *(uint32_t*)&x, yo;
    asm("tanh.approx.f16x2 %0, %1;" : "=r"(yo) : "r"(xi));
    return *(__half2*)&yo;
}

// ---------------- grid barrier (all NBLK blocks co-resident) -----------------
__device__ __forceinline__ void grid_barrier() {
    __threadfence();
    __syncthreads();
    if (threadIdx.x == 0) {
        volatile unsigned* vgen = (volatile unsigned*)&g_bar_gen;
        unsigned gen = *vgen;
        if (atomicAdd(&g_bar_count, 1u) == NBLK - 1u) {
            g_bar_count = 0u;
            __threadfence();
            *vgen = gen + 1u;
        } else {
            while (*vgen == gen) { __nanosleep(64); }
        }
    }
    __syncthreads();
}

// 64x64 block tile, 256 threads (8 warps as 2m x 4n, warp tile 32x16).
#define HM_STRIDE 40
#define HM_BUFH   (64 * HM_STRIDE)
__device__ __forceinline__ void hmma_block(
    const __half* __restrict__ Ag0, int lda,
    const __half* __restrict__ Bg0, int ldb,
    int nit, float acc[2][2][4], __half* As, __half* Bs)
{
    const int tid  = threadIdx.x;
    const int lane = tid & 31, warp = tid >> 5;

    const __half* Ag = Ag0 + (size_t)(tid >> 2) * lda + (tid & 3) * 8;
    const __half* Bg = Bg0 + (size_t)(tid >> 2) * ldb + (tid & 3) * 8;
    const uint32_t st_off = ((tid >> 2) * HM_STRIDE + (tid & 3) * 8) * 2;
    const uint32_t as_base = (uint32_t)__cvta_generic_to_shared(As);
    const uint32_t bs_base = (uint32_t)__cvta_generic_to_shared(Bs);

    const int arow = (warp >> 2) * 32 + (lane & 7) + ((lane >> 3) & 1) * 8;
    const uint32_t a_off0 = (arow * HM_STRIDE + (lane >> 4) * 8) * 2;
    const uint32_t a_off1 = a_off0 + 16 * HM_STRIDE * 2;
    const int brow = (warp & 3) * 16 + (lane & 7) + (lane >> 4) * 8;
    const uint32_t b_off = (brow * HM_STRIDE + ((lane >> 3) & 1) * 8) * 2;

    uint4 pb0 = *(const uint4*)Bg;
    uint4 pa0 = *(const uint4*)Ag;

    *(uint4*)((char*)As + st_off) = pa0;
    *(uint4*)((char*)Bs + st_off) = pb0;
    __syncthreads();

    const uint32_t BUFB = HM_BUFH * 2;
    int buf = 0;
#pragma unroll 1
    for (int it = 0; it < nit; it++) {
        uint4 pa, pb;
        const bool more = (it + 1 < nit);
        if (more) {
            pa = *(const uint4*)(Ag + (it + 1) * 32);
            pb = *(const uint4*)(Bg + (it + 1) * 32);
        }
        const uint32_t ab = as_base + buf * BUFB;
        const uint32_t bb = bs_base + buf * BUFB;
#pragma unroll
        for (int kk = 0; kk < 2; kk++) {
            uint32_t af0[4], af1[4], bf[4];
            ldsm4(af0, ab + a_off0 + kk * 32);
            ldsm4(af1, ab + a_off1 + kk * 32);
            ldsm4(bf,  bb + b_off  + kk * 32);
            mma_16816(acc[0][0], af0, bf[0], bf[1]);
            mma_16816(acc[0][1], af0, bf[2], bf[3]);
            mma_16816(acc[1][0], af1, bf[0], bf[1]);
            mma_16816(acc[1][1], af1, bf[2], bf[3]);
        }
        if (more) {
            const int nb = buf ^ 1;
            *(uint4*)((char*)As + nb * BUFB + st_off) = pa;
            *(uint4*)((char*)Bs + nb * BUFB + st_off) = pb;
            __syncthreads();
            buf = nb;
        }
    }
}

// ---------------- A precompute via HMMA: A half of g_AX ----------------------
__global__ void precompute_A_hmma() {
    __shared__ __half As[2][HM_BUFH];
    __shared__ __half Bs[2][HM_BUFH];

    float acc[2][2][4] = {};
    hmma_block(g_AX + (size_t)blockIdx.x * 64 * 512 + 256, 512,
               g_Wdx16 + (size_t)blockIdx.y * 64 * 256, 256, 8,
               acc, &As[0][0], &Bs[0][0]);

    const int lane = threadIdx.x & 31, warp = threadIdx.x >> 5;
    const int gid = lane >> 2, tig = lane & 3;
    const int mrow0 = blockIdx.x * 64 + (warp >> 2) * 32;
    const int c0 = blockIdx.y * 64 + (warp & 3) * 16;
#pragma unroll
    for (int mt = 0; mt < 2; mt++)
#pragma unroll
        for (int nt = 0; nt < 2; nt++) {
            const float* a = acc[mt][nt];
            const int r  = mrow0 + mt * 16 + gid;
            const int cc = c0 + nt * 8 + tig * 2;
            *(__half2*)&g_AX[(size_t)r * 512 + cc]       = __floats2half2_rn(a[0], a[1]);
            *(__half2*)&g_AX[(size_t)(r + 8) * 512 + cc] = __floats2half2_rn(a[2], a[3]);
        }
}

// ---------------- fused persistent loop: GEMM phase + attn/LSTM phase -------
// grid = NBLK (512) blocks, 256 threads. Per step:
//   blocks 0..383: one 64x64 HMMA tile (U1/U2/GATES) -> grid barrier ->
//   all blocks: attention (online softmax, serpentine) + LSTM for 2 batches
//   -> grid barrier.
__global__ void __launch_bounds__(256, 4)
fused_loop_kernel(const float* __restrict__ v_d,
                  const float* __restrict__ Wl,
                  const float* __restrict__ Y,
                  const float* __restrict__ W_ih)
{
    __shared__ union {
        struct { __half As[2][HM_BUFH]; __half Bs[2][HM_BUFH]; } g;
        struct {
            float ctx_ws[8][M_SZ];
            float wM[8], wS[8];
            float redy[2][8];
            float yt[2];
        } a;
    } sm;

    const int bid  = blockIdx.x;
    const int tid  = threadIdx.x;
    const int lane = tid & 31;
    const int warp = tid >> 5;
    const int wg   = warp & 3;
    const int bg   = warp >> 2;
    const int b    = bid * 2 + bg;        // this warp's batch (attn phase)

    // ---- gemm tile binding (fixed across steps -> L1-resident weights) ----
    const bool do_gemm = (bid < 384);
    const __half* GBg = nullptr; __half* GC = nullptr;
    int Gldb = 0, Gldc = 0, Gcol0 = 0, Gkoff = 0, Gx = 0;
    if (do_gemm) {
        Gx = bid & 15;
        const int y = bid >> 4;            // 0..23
        if (y < 8) {
            const int half = y >> 2;
            Gkoff = half * 256;
            GBg  = g_Wdd16 + (size_t)(y & 3) * 64 * 512 + Gkoff;
            Gldb = 512; GC = half ? g_U2h : g_U1h; Gldc = 256; Gcol0 = (y & 3) * 64;
        } else {
            GBg  = g_Whh16 + (size_t)(y - 8) * 64 * 256;
            Gldb = 256; GC = g_GATESh; Gldc = 1024; Gcol0 = (y - 8) * 64;
        }
    }

    // ---- loop-invariant attn/LSTM constants (hoisted; loaded once) --------
    const float4* AXrow = (const float4*)(g_AX + (size_t)b * T_SZ * 512) + lane;
    __half2 v2[4];
    {
        const int mb = lane * 8;
        float4 va = __ldg((const float4*)(v_d + mb));
        float4 vb = __ldg((const float4*)(v_d + mb + 4));
        v2[0] = __floats2half2_rn(va.x, va.y);
        v2[1] = __floats2half2_rn(va.z, va.w);
        v2[2] = __floats2half2_rn(vb.x, vb.y);
        v2[3] = __floats2half2_rn(vb.z, vb.w);
    }
    const float wl  = __ldg(Wl + 1 + tid);
    const float wl0 = __ldg(Wl);
    const float wi0 = __ldg(W_ih + tid);
    const float wi1 = __ldg(W_ih + P_SZ + tid);
    const float wi2 = __ldg(W_ih + 2 * P_SZ + tid);
    const float wi3 = __ldg(W_ih + 3 * P_SZ + tid);
    const float bz0 = g_bias[tid],            bz1 = g_bias[P_SZ + tid];
    const float bz2 = g_bias[2 * P_SZ + tid], bz3 = g_bias[3 * P_SZ + tid];

#pragma unroll 1
    for (int step = 0; step < TS; step++) {
        // ================= GEMM phase =================
        if (do_gemm) {
            float acc[2][2][4] = {};
            hmma_block(g_HCh + (size_t)Gx * 64 * 512 + Gkoff, 512,
                       GBg, Gldb, 8, acc, &sm.g.As[0][0], &sm.g.Bs[0][0]);

            const int gid = lane >> 2, tig = lane & 3;
            const int mrow0 = Gx * 64 + (warp >> 2) * 32;
            const int c0 = Gcol0 + (warp & 3) * 16;
#pragma unroll
            for (int mt = 0; mt < 2; mt++)
#pragma unroll
                for (int nt = 0; nt < 2; nt++) {
                    const float* a = acc[mt][nt];
                    const int r  = mrow0 + mt * 16 + gid;
                    const int cc = c0 + nt * 8 + tig * 2;
                    *(__half2*)&GC[(size_t)r * Gldc + cc] =
                        __floats2half2_rn(a[0], a[1]);
                    *(__half2*)&GC[(size_t)(r + 8) * Gldc + cc] =
                        __floats2half2_rn(a[2], a[3]);
                }
        }
        grid_barrier();

        // ================= attention + LSTM phase =================
        // serpentine direction
        const int dir   = step & 1;
        const int r0    = dir ? (T_SZ - 1 - wg) : wg;
        const int rstep = dir ? -4 : 4;

        // per-lane u slices as half2 (fresh each step)
        __half2 u2[4];
        {
            uint4 u1r = __ldg((const uint4*)(g_U1h + b * M_SZ) + lane);
            uint4 u2r = __ldg((const uint4*)(g_U2h + b * M_SZ) + lane);
            const __half2* p1 = (const __half2*)&u1r;
            const __half2* p2 = (const __half2*)&u2r;
#pragma unroll
            for (int j = 0; j < 4; j++) u2[j] = __hadd2(p1[j], p2[j]);
        }

        float C[8] = {0, 0, 0, 0, 0, 0, 0, 0};
        float Mx = -1e30f, S = 0.0f;

        float4 a0 = __ldg(AXrow + (size_t)r0 * 64);
        float4 x0 = __ldg(AXrow + (size_t)r0 * 64 + 32);
        float4 a1 = __ldg(AXrow + (size_t)(r0 + rstep) * 64);
        float4 x1 = __ldg(AXrow + (size_t)(r0 + rstep) * 64 + 32);

#pragma unroll 4
        for (int i = 0; i < 32; i++) {
            float4 a2, x2;
            if (i < 30) {
                const int rn = r0 + (i + 2) * rstep;
                a2 = __ldg(AXrow + (size_t)rn * 64);
                x2 = __ldg(AXrow + (size_t)rn * 64 + 32);
            }

            const __half2* ahp = (const __half2*)&a0;
            const __half2* xhp = (const __half2*)&x0;
            __half2 acch = __floats2half2_rn(0.0f, 0.0f);
            float xv[8];
#pragma unroll
            for (int j = 0; j < 4; j++) {
                __half2 s  = __hadd2(u2[j], ahp[j]);
                __half2 th = h2tanh_fast(s);
                acch = __hfma2(v2[j], th, acch);
                float2 xf = __half22float2(xhp[j]);
                xv[2 * j] = xf.x; xv[2 * j + 1] = xf.y;
            }
            float acc = __low2float(acch) + __high2float(acch);
#pragma unroll
            for (int o = 16; o; o >>= 1) acc += __shfl_xor_sync(0xffffffffu, acc, o);

            if (acc <= Mx) {
                float e = __expf(acc - Mx);
                S += e;
#pragma unroll
                for (int j = 0; j < 8; j++) C[j] = fmaf(e, xv[j], C[j]);
            } else {
                float f = __expf(Mx - acc);
                S = fmaf(S, f, 1.0f);
#pragma unroll
                for (int j = 0; j < 8; j++) C[j] = fmaf(C[j], f, xv[j]);
                Mx = acc;
            }

            a0 = a1; x0 = x1; a1 = a2; x1 = x2;
        }

        if (lane == 0) { sm.a.wM[warp] = Mx; sm.a.wS[warp] = S; }
        *(float4*)&sm.a.ctx_ws[warp][lane * 8] =
            make_float4(C[0], C[1], C[2], C[3]);
        *(float4*)&sm.a.ctx_ws[warp][lane * 8 + 4] =
            make_float4(C[4], C[5], C[6], C[7]);
        __syncthreads();

        float cg[2];
#pragma unroll
        for (int g = 0; g < 2; g++) {
            float Mg = fmaxf(fmaxf(sm.a.wM[4 * g], sm.a.wM[4 * g + 1]),
                             fmaxf(sm.a.wM[4 * g + 2], sm.a.wM[4 * g + 3]));
            float Sg = 0.0f, c = 0.0f;
#pragma unroll
            for (int w = 0; w < 4; w++) {
                float f = __expf(sm.a.wM[4 * g + w] - Mg);
                Sg = fmaf(sm.a.wS[4 * g + w], f, Sg);
                c  = fmaf(f, sm.a.ctx_ws[4 * g + w][tid], c);
            }
            cg[g] = c / Sg;
        }

        if (step == TS - 1) {
            g_CTX[(bid * 2)     * M_SZ + tid] = cg[0];
            g_CTX[(bid * 2 + 1) * M_SZ + tid] = cg[1];
        }

#pragma unroll
        for (int g = 0; g < 2; g++) {
            float yv = wl * cg[g];
#pragma unroll
            for (int o = 16; o; o >>= 1) yv += __shfl_xor_sync(0xffffffffu, yv, o);
            if (lane == 0) sm.a.redy[g][warp] = yv;
        }
        __syncthreads();
        if (tid < 2) {
            float s = sm.a.redy[tid][0] + sm.a.redy[tid][1] + sm.a.redy[tid][2]
                    + sm.a.redy[tid][3] + sm.a.redy[tid][4] + sm.a.redy[tid][5]
                    + sm.a.redy[tid][6] + sm.a.redy[tid][7];
            sm.a.yt[tid] = fmaf(wl0, Y[(size_t)(bid * 2 + tid) * TS + step], s);
        }
        __syncthreads();

        const int p = tid;
#pragma unroll
        for (int g = 0; g < 2; g++) {
            const int bb = bid * 2 + g;
            const float yt = sm.a.yt[g];
            const __half* gr = g_GATESh + (size_t)bb * 4 * P_SZ;
            float ig = __half2float(gr[p])            + yt * wi0 + bz0;
            float fg = __half2float(gr[P_SZ + p])     + yt * wi1 + bz1;
            float gg = __half2float(gr[2 * P_SZ + p]) + yt * wi2 + bz2;
            float og = __half2float(gr[3 * P_SZ + p]) + yt * wi3 + bz3;

            float cold = g_HC[(size_t)bb * 512 + 256 + p];
            float si = 1.0f / (1.0f + __expf(-ig));
            float sf = 1.0f / (1.0f + __expf(-fg));
            float so = 1.0f / (1.0f + __expf(-og));
            float cn = sf * cold + si * tanhf(gg);
            float hn = so * tanhf(cn);

            g_HC[(size_t)bb * 512 + p]        = hn;
            g_HC[(size_t)bb * 512 + 256 + p]  = cn;
            g_HCh[(size_t)bb * 512 + p]       = __float2half_rn(hn);
            g_HCh[(size_t)bb * 512 + 256 + p] = __float2half_rn(cn);
        }

        if (step < TS - 1) grid_barrier();
    }
}

// ---------------- final head: out = ([h,ctx] @ Wb^T + b) @ vb^T + vb_b -----
__global__ void final_head_kernel(const float* __restrict__ Wb_w,
                                  const float* __restrict__ Wb_b,
                                  const float* __restrict__ vb_w,
                                  const float* __restrict__ vb_b,
                                  float* __restrict__ out)
{
    const int b   = blockIdx.x;
    const int tid = threadIdx.x;  // 0..255 = p
    __shared__ float hc_s[512];
    __shared__ float red[8];

    hc_s[tid]        = g_HC[(size_t)b * 512 + tid];        // h
    hc_s[P_SZ + tid] = g_CTX[(size_t)b * M_SZ + tid];      // ctx
    __syncthreads();

    const float* wr = Wb_w + (size_t)tid * (P_SZ + M_SZ);
    float t = __ldg(Wb_b + tid);
#pragma unroll 4
    for (int k = 0; k < 2 * P_SZ; k++)
        t = fmaf(__ldg(wr + k), hc_s[k], t);
    float val = __ldg(vb_w + tid) * t;

    int lane = tid & 31, warp = tid >> 5;
#pragma unroll
    for (int o = 16; o; o >>= 1) val += __shfl_xor_sync(0xffffffffu, val, o);
    if (lane == 0) red[warp] = val;
    __syncthreads();
    if (tid == 0)
        out[b] = vb_b[0] + red[0] + red[1] + red[2] + red[3]
                         + red[4] + red[5] + red[6] + red[7];
}

// ---------------- launch ----------------------------------------------------
extern "C" void kernel_launch(void* const* d_in, const int* in_sizes, int n_in,
                              void* d_out, int out_size)
{
    const float* Y    = (const float*)d_in[0];
    const float* X    = (const float*)d_in[1];
    const float* WU_d = (const float*)d_in[2];
    const float* v_d  = (const float*)d_in[3];
    const float* Wl   = (const float*)d_in[4];
    const float* W_ih = (const float*)d_in[5];
    const float* W_hh = (const float*)d_in[6];
    const float* b_ih = (const float*)d_in[7];
    const float* b_hh = (const float*)d_in[8];
    const float* Wb_w = (const float*)d_in[9];
    const float* Wb_b = (const float*)d_in[10];
    const float* vb_w = (const float*)d_in[11];
    const float* vb_b = (const float*)d_in[12];
    float* out = (float*)d_out;

    // maximize shared carveout so 4 blocks/SM is guaranteed for the
    // persistent kernel (20.5KB static smem * 4 = 82KB)
    static bool attr_set = false;
    if (!attr_set) {
        cudaFuncSetAttribute(fused_loop_kernel,
                             cudaFuncAttributePreferredSharedMemoryCarveout, 100);
        attr_set = true;
    }

    // init h, c = 0 (fp32 + fp16 mirrors)
    init_hc_kernel<<<(B_SZ * 512 + 255) / 256, 256>>>();

    // X -> interleaved AX (X half) fp16 ; weights -> fp16 ; fused bias
    convert_x_kernel<<<(T_SZ * B_SZ) / 4, 256>>>(X);
    convert_w_kernel<<<1024, 256>>>(WU_d, W_hh, b_ih, b_hh);

    // A half of g_AX = X16 @ Wdx^T (HMMA)
    precompute_A_hmma<<<dim3((B_SZ * T_SZ) / 64, M_SZ / 64), 256>>>();

    // the entire 127-step recurrence in one persistent kernel
    fused_loop_kernel<<<NBLK, 256>>>(v_d, Wl, Y, W_ih);

    final_head_kernel<<<B_SZ, 256>>>(Wb_w, Wb_b, vb_w, vb_b, out);
}

// round 15
// speedup vs baseline: 1.3349x; 1.3349x over previous
#include <cuda_runtime.h>
#include <cuda_fp16.h>
#include <cstdint>
#include <cstddef>

#define B_SZ 1024
#define T_SZ 128
#define M_SZ 256
#define P_SZ 256
#define TS   127   // T-1 recurrence steps

// ---------------- scratch (static device globals) ---------------------------
// interleaved per-(b,t) row: [ A[0..255] | X[0..255] ] fp16, stride 512
__device__ __half g_AX[(size_t)B_SZ * T_SZ * 512];
__device__ __half g_HCh[B_SZ * 512];                 // fp16 mirror of [h|c]
__device__ __half g_Wdd16[256 * 512];                // WU_d[:, :512] fp16
__device__ __half g_Whh16[1024 * 256];               // W_hh fp16
__device__ __half g_Wdx16[256 * 256];                // WU_d[:, 512:768] fp16
__device__ float  g_bias[4 * P_SZ];                  // b_ih + b_hh
__device__ __half g_U1h[B_SZ * M_SZ];                // d-part preact, K 0:256 (fp16)
__device__ __half g_U2h[B_SZ * M_SZ];                // d-part preact, K 256:512 (fp16)
__device__ __half g_GATESh[B_SZ * 4 * P_SZ];         // h @ W_hh^T (fp16)
__device__ float  g_HC[B_SZ * 512];                  // fp32 master [h|c]
__device__ float  g_CTX[B_SZ * M_SZ];                // attention context (last step)

// ---------------- init ------------------------------------------------------
__global__ void init_hc_kernel() {
    int i = blockIdx.x * blockDim.x + threadIdx.x;
    if (i < B_SZ * 512) { g_HC[i] = 0.0f; g_HCh[i] = __float2half_rn(0.0f); }
}

// ---------------- X (t,b,m) fp32 -> g_AX[b,t, 256+m] fp16 -------------------
__global__ void convert_x_kernel(const float* __restrict__ X) {
    int row = blockIdx.x * 4 + (threadIdx.x >> 6);   // row = t*B + b
    int c4  = (threadIdx.x & 63) * 4;
    int t = row >> 10;
    int b = row & 1023;
    float4 v = __ldg((const float4*)(X + (size_t)row * M_SZ + c4));
    __half2* dst = (__half2*)(g_AX + ((size_t)(b << 7) + t) * 512 + 256 + c4);
    dst[0] = __floats2half2_rn(v.x, v.y);
    dst[1] = __floats2half2_rn(v.z, v.w);
}

// ---------------- weights -> fp16, fused bias -------------------------------
__global__ void convert_w_kernel(const float* __restrict__ WU_d,
                                 const float* __restrict__ W_hh,
                                 const float* __restrict__ b_ih,
                                 const float* __restrict__ b_hh) {
    int i = blockIdx.x * 256 + threadIdx.x;          // 0 .. 262143
    if (i < 256 * 512) {
        int r = i >> 9, k = i & 511;
        g_Wdd16[i] = __float2half_rn(WU_d[r * 768 + k]);
    }
    if (i < 256 * 256) {
        int r = i >> 8, k = i & 255;
        g_Wdx16[i] = __float2half_rn(WU_d[r * 768 + 512 + k]);
    }
    if (i < 1024 * 256) {
        g_Whh16[i] = __float2half_rn(W_hh[i]);
    }
    if (i < 1024) {
        g_bias[i] = b_ih[i] + b_hh[i];
    }
}

// ---------------- HMMA helpers ----------------------------------------------
__device__ __forceinline__ void ldsm4(uint32_t* r, uint32_t addr) {
    asm volatile("ldmatrix.sync.aligned.m8n8.x4.shared.b16 {%0,%1,%2,%3}, [%4];"
                 : "=r"(r[0]), "=r"(r[1]), "=r"(r[2]), "=r"(r[3]) : "r"(addr));
}

__device__ __forceinline__ void mma_16816(float* acc, const uint32_t* a,
                                          uint32_t b0, uint32_t b1) {
    asm volatile(
        "mma.sync.aligned.m16n8k16.row.col.f32.f16.f16.f32 "
        "{%0,%1,%2,%3},{%4,%5,%6,%7},{%8,%9},{%0,%1,%2,%3};"
        : "+f"(acc[0]), "+f"(acc[1]), "+f"(acc[2]), "+f"(acc[3])
        : "r"(a[0]), "r"(a[1]), "r"(a[2]), "r"(a[3]), "r"(b0), "r"(b1));
}

__device__ __forceinline__ __half2 h2tanh_fast(__half2 x) {
    uint32_t xi = *(uint32_t*)&x, yo;
    asm("tanh.approx.f16x2 %0, %1;" : "=r"(yo) : "r"(xi));
    return *(__half2*)&yo;
}

// 64x64 block tile, 256 threads (8 warps as 2m x 4n, warp tile 32x16).
// K-chunk = 64 halves per stage (nit stages of k=64) -> half the latency chain
// vs k=32. Tile: 64 rows x 72 halves (pad 8) -> conflict-free STS.128 + LDSM.
// PDL=true: weight tile-0 loads issued BEFORE the grid dependency sync.
#define HM_STRIDE 72
#define HM_BUFH   (64 * HM_STRIDE)
template<bool PDL>
__device__ __forceinline__ void hmma_block(
    const __half* __restrict__ Ag0, int lda,
    const __half* __restrict__ Bg0, int ldb,
    int nit, float acc[2][2][4], __half* As, __half* Bs)
{
    const int tid  = threadIdx.x;
    const int lane = tid & 31, warp = tid >> 5;

    // per-thread load slots: rows (tid>>3) and (tid>>3)+32, col (tid&7)*8
    const int lrow = tid >> 3;
    const int lcol = (tid & 7) * 8;
    const __half* Ag = Ag0 + (size_t)lrow * lda + lcol;
    const __half* Bg = Bg0 + (size_t)lrow * ldb + lcol;
    const size_t arow2 = (size_t)32 * lda;
    const size_t brow2 = (size_t)32 * ldb;

    const uint32_t st0 = (uint32_t)(lrow * HM_STRIDE + lcol) * 2;
    const uint32_t st1 = st0 + 32 * HM_STRIDE * 2;
    const uint32_t as_base = (uint32_t)__cvta_generic_to_shared(As);
    const uint32_t bs_base = (uint32_t)__cvta_generic_to_shared(Bs);

    const int arow = (warp >> 2) * 32 + (lane & 7) + ((lane >> 3) & 1) * 8;
    const uint32_t a_off0 = (arow * HM_STRIDE + (lane >> 4) * 8) * 2;
    const uint32_t a_off1 = a_off0 + 16 * HM_STRIDE * 2;
    const int brow = (warp & 3) * 16 + (lane & 7) + (lane >> 4) * 8;
    const uint32_t b_off = (brow * HM_STRIDE + ((lane >> 3) & 1) * 8) * 2;

    // stage 0: weight (B) loads first -- independent of predecessor kernel
    uint4 pb0 = *(const uint4*)Bg;
    uint4 pb1 = *(const uint4*)(Bg + brow2);
    if (PDL) cudaGridDependencySynchronize();
    uint4 pa0 = *(const uint4*)Ag;
    uint4 pa1 = *(const uint4*)(Ag + arow2);

    *(uint4*)((char*)As + st0) = pa0;
    *(uint4*)((char*)As + st1) = pa1;
    *(uint4*)((char*)Bs + st0) = pb0;
    *(uint4*)((char*)Bs + st1) = pb1;
    __syncthreads();

    const uint32_t BUFB = HM_BUFH * 2;
    int buf = 0;
#pragma unroll 1
    for (int it = 0; it < nit; it++) {
        uint4 na0, na1, nb0, nb1;
        const bool more = (it + 1 < nit);
        if (more) {
            const int ko = (it + 1) * 64;
            na0 = *(const uint4*)(Ag + ko);
            na1 = *(const uint4*)(Ag + arow2 + ko);
            nb0 = *(const uint4*)(Bg + ko);
            nb1 = *(const uint4*)(Bg + brow2 + ko);
        }
        const uint32_t ab = as_base + buf * BUFB;
        const uint32_t bb = bs_base + buf * BUFB;
#pragma unroll
        for (int kk = 0; kk < 4; kk++) {
            uint32_t af0[4], af1[4], bf[4];
            ldsm4(af0, ab + a_off0 + kk * 32);
            ldsm4(af1, ab + a_off1 + kk * 32);
            ldsm4(bf,  bb + b_off  + kk * 32);
            mma_16816(acc[0][0], af0, bf[0], bf[1]);
            mma_16816(acc[0][1], af0, bf[2], bf[3]);
            mma_16816(acc[1][0], af1, bf[0], bf[1]);
            mma_16816(acc[1][1], af1, bf[2], bf[3]);
        }
        if (more) {
            const int nb = buf ^ 1;
            *(uint4*)((char*)As + nb * BUFB + st0) = na0;
            *(uint4*)((char*)As + nb * BUFB + st1) = na1;
            *(uint4*)((char*)Bs + nb * BUFB + st0) = nb0;
            *(uint4*)((char*)Bs + nb * BUFB + st1) = nb1;
            __syncthreads();
            buf = nb;
        }
    }
}

// ---------------- per-step GEMMs via HMMA, uniform K=256 tiles ---------------
// grid (16, 24): y 0..3 -> U1 (K 0:256); y 4..7 -> U2 (K 256:512);
//                y 8..23 -> GATES (K=256). Outputs fp16. nit=4 (k=64 chunks).
__global__ void step_gemm_hmma() {
    __shared__ __half As[2][HM_BUFH];
    __shared__ __half Bs[2][HM_BUFH];

    const int y = blockIdx.y;
    const __half* Bg; __half* C; int ldb, ldc, col0, koff;
    if (y < 8) {
        const int half = y >> 2;                 // 0 -> U1, 1 -> U2
        koff = half * 256;
        Bg   = g_Wdd16 + (size_t)(y & 3) * 64 * 512 + koff;
        ldb  = 512; C = half ? g_U2h : g_U1h; ldc = 256; col0 = (y & 3) * 64;
    } else {
        koff = 0;
        Bg   = g_Whh16 + (size_t)(y - 8) * 64 * 256;
        ldb  = 256; C = g_GATESh; ldc = 1024; col0 = (y - 8) * 64;
    }

    float acc[2][2][4] = {};
    hmma_block<true>(g_HCh + (size_t)blockIdx.x * 64 * 512 + koff, 512,
                     Bg, ldb, 4, acc, &As[0][0], &Bs[0][0]);

    const int lane = threadIdx.x & 31, warp = threadIdx.x >> 5;
    const int gid = lane >> 2, tig = lane & 3;
    const int mrow0 = blockIdx.x * 64 + (warp >> 2) * 32;
    const int c0 = col0 + (warp & 3) * 16;
#pragma unroll
    for (int mt = 0; mt < 2; mt++)
#pragma unroll
        for (int nt = 0; nt < 2; nt++) {
            const float* a = acc[mt][nt];
            const int r  = mrow0 + mt * 16 + gid;
            const int cc = c0 + nt * 8 + tig * 2;
            *(__half2*)&C[(size_t)r * ldc + cc]       = __floats2half2_rn(a[0], a[1]);
            *(__half2*)&C[(size_t)(r + 8) * ldc + cc] = __floats2half2_rn(a[2], a[3]);
        }
}

// ---------------- A precompute via HMMA: A half of g_AX ----------------------
__global__ void precompute_A_hmma() {
    __shared__ __half As[2][HM_BUFH];
    __shared__ __half Bs[2][HM_BUFH];

    float acc[2][2][4] = {};
    hmma_block<false>(g_AX + (size_t)blockIdx.x * 64 * 512 + 256, 512,
                      g_Wdx16 + (size_t)blockIdx.y * 64 * 256, 256, 4,
                      acc, &As[0][0], &Bs[0][0]);

    const int lane = threadIdx.x & 31, warp = threadIdx.x >> 5;
    const int gid = lane >> 2, tig = lane & 3;
    const int mrow0 = blockIdx.x * 64 + (warp >> 2) * 32;
    const int c0 = blockIdx.y * 64 + (warp & 3) * 16;
#pragma unroll
    for (int mt = 0; mt < 2; mt++)
#pragma unroll
        for (int nt = 0; nt < 2; nt++) {
            const float* a = acc[mt][nt];
            const int r  = mrow0 + mt * 16 + gid;
            const int cc = c0 + nt * 8 + tig * 2;
            *(__half2*)&g_AX[(size_t)r * 512 + cc]       = __floats2half2_rn(a[0], a[1]);
            *(__half2*)&g_AX[(size_t)(r + 8) * 512 + cc] = __floats2half2_rn(a[2], a[3]);
        }
}

// ---------------- fused attention (online softmax) + LSTM step --------------
// 512 blocks, 2 batches per block; warps 0-3 -> batch0, warps 4-7 -> batch1.
// Serpentine t-sweep (L2-resident re-reads); PDL prefetch + early trigger.
__global__ void __launch_bounds__(256, 4)
attn_lstm_kernel(const float* __restrict__ v_d,
                 const float* __restrict__ Wl,
                 const float* __restrict__ Y,
                 const float* __restrict__ W_ih,
                 int t_step)
{
    __shared__ float ctx_ws[8][M_SZ];
    __shared__ float wM[8], wS[8];
    __shared__ float redy[2][8];
    __shared__ float yt_s[2];

    const int tid  = threadIdx.x;     // 0..255
    const int lane = tid & 31;
    const int warp = tid >> 5;
    const int wg   = warp & 3;        // t offset within batch
    const int bg   = warp >> 2;       // which batch of the pair
    const int b    = blockIdx.x * 2 + bg;

    // serpentine direction
    const int dir   = t_step & 1;
    const int r0    = dir ? (T_SZ - 1 - wg) : wg;
    const int rstep = dir ? -4 : 4;

    // ---- prologue independent of predecessor: AX pipeline warm-up + v_d ----
    const float4* AXrow = (const float4*)(g_AX + (size_t)b * T_SZ * 512) + lane;
    float4 a0 = __ldg(AXrow + (size_t)r0 * 64);
    float4 x0 = __ldg(AXrow + (size_t)r0 * 64 + 32);
    float4 a1 = __ldg(AXrow + (size_t)(r0 + rstep) * 64);
    float4 x1 = __ldg(AXrow + (size_t)(r0 + rstep) * 64 + 32);
    const int mb = lane * 8;
    float4 va  = __ldg((const float4*)(v_d + mb));
    float4 vb  = __ldg((const float4*)(v_d + mb + 4));

    // ---- wait for step_gemm's U/GATES ----
    cudaGridDependencySynchronize();

    // per-lane u,v slices as half2 (m = lane*8 .. lane*8+7), reused 32x
    __half2 u2[4], v2[4];
    {
        uint4 u1r = __ldg((const uint4*)(g_U1h + b * M_SZ) + lane);
        uint4 u2r = __ldg((const uint4*)(g_U2h + b * M_SZ) + lane);
        const __half2* p1 = (const __half2*)&u1r;
        const __half2* p2 = (const __half2*)&u2r;
#pragma unroll
        for (int j = 0; j < 4; j++) u2[j] = __hadd2(p1[j], p2[j]);
        v2[0] = __floats2half2_rn(va.x, va.y);
        v2[1] = __floats2half2_rn(va.z, va.w);
        v2[2] = __floats2half2_rn(vb.x, vb.y);
        v2[3] = __floats2half2_rn(vb.z, vb.w);
    }

    // single pass: logits + online softmax + ctx accumulation
    float C[8] = {0, 0, 0, 0, 0, 0, 0, 0};
    float Mx = -1e30f, S = 0.0f;

#pragma unroll 4
    for (int i = 0; i < 32; i++) {
        float4 a2, x2;
        if (i < 30) {
            const int rn = r0 + (i + 2) * rstep;
            a2 = __ldg(AXrow + (size_t)rn * 64);
            x2 = __ldg(AXrow + (size_t)rn * 64 + 32);
        }

        // logit partial from this lane's 8 m-values (f16x2 path)
        const __half2* ahp = (const __half2*)&a0;
        const __half2* xhp = (const __half2*)&x0;
        __half2 acch = __floats2half2_rn(0.0f, 0.0f);
        float xv[8];
#pragma unroll
        for (int j = 0; j < 4; j++) {
            __half2 s  = __hadd2(u2[j], ahp[j]);
            __half2 th = h2tanh_fast(s);
            acch = __hfma2(v2[j], th, acch);
            float2 xf = __half22float2(xhp[j]);
            xv[2 * j] = xf.x; xv[2 * j + 1] = xf.y;
        }
        float acc = __low2float(acch) + __high2float(acch);
#pragma unroll
        for (int o = 16; o; o >>= 1) acc += __shfl_xor_sync(0xffffffffu, acc, o);
        // acc = l_t, uniform across warp

        if (acc <= Mx) {                 // warp-uniform branch
            float e = __expf(acc - Mx);
            S += e;
#pragma unroll
            for (int j = 0; j < 8; j++) C[j] = fmaf(e, xv[j], C[j]);
        } else {
            float f = __expf(Mx - acc);
            S = fmaf(S, f, 1.0f);
#pragma unroll
            for (int j = 0; j < 8; j++) C[j] = fmaf(C[j], f, xv[j]);
            Mx = acc;
        }

        a0 = a1; x0 = x1; a1 = a2; x1 = x2;
    }

    // per-warp results -> smem
    if (lane == 0) { wM[warp] = Mx; wS[warp] = S; }
    *(float4*)&ctx_ws[warp][lane * 8]     = make_float4(C[0], C[1], C[2], C[3]);
    *(float4*)&ctx_ws[warp][lane * 8 + 4] = make_float4(C[4], C[5], C[6], C[7]);
    __syncthreads();

    // per-batch combine (each thread computes ctx[m=tid] for both batches)
    float cg[2];
#pragma unroll
    for (int g = 0; g < 2; g++) {
        float Mg = fmaxf(fmaxf(wM[4 * g], wM[4 * g + 1]),
                         fmaxf(wM[4 * g + 2], wM[4 * g + 3]));
        float Sg = 0.0f, c = 0.0f;
#pragma unroll
        for (int w = 0; w < 4; w++) {
            float f = __expf(wM[4 * g + w] - Mg);
            Sg = fmaf(wS[4 * g + w], f, Sg);
            c  = fmaf(f, ctx_ws[4 * g + w][tid], c);
        }
        cg[g] = c / Sg;
    }

    if (t_step == TS - 1) {
        g_CTX[(blockIdx.x * 2)     * M_SZ + tid] = cg[0];
        g_CTX[(blockIdx.x * 2 + 1) * M_SZ + tid] = cg[1];
    }

    // y_tilde per batch: Wl[0]*y_t + sum_m Wl[1+m]*ctx[m]
    const float wl = __ldg(Wl + 1 + tid);
#pragma unroll
    for (int g = 0; g < 2; g++) {
        float yv = wl * cg[g];
#pragma unroll
        for (int o = 16; o; o >>= 1) yv += __shfl_xor_sync(0xffffffffu, yv, o);
        if (lane == 0) redy[g][warp] = yv;
    }
    __syncthreads();
    if (tid < 2) {
        float s = redy[tid][0] + redy[tid][1] + redy[tid][2] + redy[tid][3]
                + redy[tid][4] + redy[tid][5] + redy[tid][6] + redy[tid][7];
        yt_s[tid] = fmaf(__ldg(Wl),
                         Y[(size_t)(blockIdx.x * 2 + tid) * TS + t_step], s);
    }
    __syncthreads();

    // fused LSTM pointwise update for both batches
    const int p = tid;
    const float wi0 = __ldg(W_ih + p);
    const float wi1 = __ldg(W_ih + P_SZ + p);
    const float wi2 = __ldg(W_ih + 2 * P_SZ + p);
    const float wi3 = __ldg(W_ih + 3 * P_SZ + p);
    const float bz0 = g_bias[p], bz1 = g_bias[P_SZ + p];
    const float bz2 = g_bias[2 * P_SZ + p], bz3 = g_bias[3 * P_SZ + p];

#pragma unroll
    for (int g = 0; g < 2; g++) {
        const int bb = blockIdx.x * 2 + g;
        const float yt = yt_s[g];
        const __half* gr = g_GATESh + (size_t)bb * 4 * P_SZ;
        float ig = __half2float(gr[p])            + yt * wi0 + bz0;
        float fg = __half2float(gr[P_SZ + p])     + yt * wi1 + bz1;
        float gg = __half2float(gr[2 * P_SZ + p]) + yt * wi2 + bz2;
        float og = __half2float(gr[3 * P_SZ + p]) + yt * wi3 + bz3;

        float cold = g_HC[(size_t)bb * 512 + 256 + p];
        float si = 1.0f / (1.0f + __expf(-ig));
        float sf = 1.0f / (1.0f + __expf(-fg));
        float so = 1.0f / (1.0f + __expf(-og));
        float cn = sf * cold + si * tanhf(gg);
        float hn = so * tanhf(cn);

        g_HC[(size_t)bb * 512 + p]        = hn;
        g_HC[(size_t)bb * 512 + 256 + p]  = cn;
        g_HCh[(size_t)bb * 512 + p]       = __float2half_rn(hn);
        g_HCh[(size_t)bb * 512 + 256 + p] = __float2half_rn(cn);
    }

    // make h,c visible, then let the next step's GEMM launch
    __threadfence();
    __syncthreads();
    cudaTriggerProgrammaticLaunchCompletion();
}

// ---------------- final head: out = ([h,ctx] @ Wb^T + b) @ vb^T + vb_b -----
__global__ void final_head_kernel(const float* __restrict__ Wb_w,
                                  const float* __restrict__ Wb_b,
                                  const float* __restrict__ vb_w,
                                  const float* __restrict__ vb_b,
                                  float* __restrict__ out)
{
    const int b   = blockIdx.x;
    const int tid = threadIdx.x;  // 0..255 = p
    __shared__ float hc_s[512];
    __shared__ float red[8];

    hc_s[tid]        = g_HC[(size_t)b * 512 + tid];        // h
    hc_s[P_SZ + tid] = g_CTX[(size_t)b * M_SZ + tid];      // ctx
    __syncthreads();

    const float* wr = Wb_w + (size_t)tid * (P_SZ + M_SZ);
    float t = __ldg(Wb_b + tid);
#pragma unroll 4
    for (int k = 0; k < 2 * P_SZ; k++)
        t = fmaf(__ldg(wr + k), hc_s[k], t);
    float val = __ldg(vb_w + tid) * t;

    int lane = tid & 31, warp = tid >> 5;
#pragma unroll
    for (int o = 16; o; o >>= 1) val += __shfl_xor_sync(0xffffffffu, val, o);
    if (lane == 0) red[warp] = val;
    __syncthreads();
    if (tid == 0)
        out[b] = vb_b[0] + red[0] + red[1] + red[2] + red[3]
                         + red[4] + red[5] + red[6] + red[7];
}

// ---------------- launch ----------------------------------------------------
extern "C" void kernel_launch(void* const* d_in, const int* in_sizes, int n_in,
                              void* d_out, int out_size)
{
    const float* Y    = (const float*)d_in[0];
    const float* X    = (const float*)d_in[1];
    const float* WU_d = (const float*)d_in[2];
    const float* v_d  = (const float*)d_in[3];
    const float* Wl   = (const float*)d_in[4];
    const float* W_ih = (const float*)d_in[5];
    const float* W_hh = (const float*)d_in[6];
    const float* b_ih = (const float*)d_in[7];
    const float* b_hh = (const float*)d_in[8];
    const float* Wb_w = (const float*)d_in[9];
    const float* Wb_b = (const float*)d_in[10];
    const float* vb_w = (const float*)d_in[11];
    const float* vb_b = (const float*)d_in[12];
    float* out = (float*)d_out;

    // init h, c = 0 (fp32 + fp16 mirrors)
    init_hc_kernel<<<(B_SZ * 512 + 255) / 256, 256>>>();

    // X -> interleaved AX (X half) fp16 ; weights -> fp16 ; fused bias
    convert_x_kernel<<<(T_SZ * B_SZ) / 4, 256>>>(X);
    convert_w_kernel<<<1024, 256>>>(WU_d, W_hh, b_ih, b_hh);

    // A half of g_AX = X16 @ Wdx^T (HMMA)
    precompute_A_hmma<<<dim3((B_SZ * T_SZ) / 64, M_SZ / 64), 256>>>();

    // PDL-chained recurrence
    cudaLaunchAttribute pdl[1];
    pdl[0].id = cudaLaunchAttributeProgrammaticStreamSerialization;
    pdl[0].val.programmaticStreamSerializationAllowed = 1;

    cudaLaunchConfig_t cfg_g = {};
    cfg_g.gridDim  = dim3(B_SZ / 64, 24);
    cfg_g.blockDim = dim3(256);
    cfg_g.stream   = 0;
    cfg_g.attrs    = pdl;
    cfg_g.numAttrs = 1;

    cudaLaunchConfig_t cfg_a = {};
    cfg_a.gridDim  = dim3(B_SZ / 2);
    cfg_a.blockDim = dim3(256);
    cfg_a.stream   = 0;
    cfg_a.attrs    = pdl;
    cfg_a.numAttrs = 1;

    for (int t = 0; t < TS; t++) {
        cudaLaunchKernelEx(&cfg_g, step_gemm_hmma);
        cudaLaunchKernelEx(&cfg_a, attn_lstm_kernel, v_d, Wl, Y, W_ih, t);
    }

    final_head_kernel<<<B_SZ, 256>>>(Wb_w, Wb_b, vb_w, vb_b, out);
}

// round 16
// speedup vs baseline: 1.3376x; 1.0020x over previous
#include <cuda_runtime.h>
#include <cuda_fp16.h>
#include <cstdint>
#include <cstddef>

#define B_SZ 1024
#define T_SZ 128
#define M_SZ 256
#define P_SZ 256
#define TS   127   // T-1 recurrence steps

// ---------------- scratch (static device globals) ---------------------------
// interleaved per-(b,t) row: [ A[0..255] | X[0..255] ] fp16, stride 512
__device__ __half g_AX[(size_t)B_SZ * T_SZ * 512];
__device__ __half g_HCh[B_SZ * 512];                 // fp16 mirror of [h|c]
__device__ __half g_Wdd16[256 * 512];                // WU_d[:, :512] fp16
__device__ __half g_Whh16[1024 * 256];               // W_hh fp16
__device__ __half g_Wdx16[256 * 256];                // WU_d[:, 512:768] fp16
__device__ float  g_bias[4 * P_SZ];                  // b_ih + b_hh
__device__ __half g_U1h[B_SZ * M_SZ];                // d-part preact, K 0:256 (fp16)
__device__ __half g_U2h[B_SZ * M_SZ];                // d-part preact, K 256:512 (fp16)
__device__ __half g_GATESh[B_SZ * 4 * P_SZ];         // h @ W_hh^T (fp16)
__device__ float  g_HC[B_SZ * 512];                  // fp32 master [h|c]
__device__ float  g_CTX[B_SZ * M_SZ];                // attention context (last step)

// ---------------- init ------------------------------------------------------
__global__ void init_hc_kernel() {
    int i = blockIdx.x * blockDim.x + threadIdx.x;
    if (i < B_SZ * 512) { g_HC[i] = 0.0f; g_HCh[i] = __float2half_rn(0.0f); }
}

// ---------------- X (t,b,m) fp32 -> g_AX[b,t, 256+m] fp16 -------------------
__global__ void convert_x_kernel(const float* __restrict__ X) {
    int row = blockIdx.x * 4 + (threadIdx.x >> 6);   // row = t*B + b
    int c4  = (threadIdx.x & 63) * 4;
    int t = row >> 10;
    int b = row & 1023;
    float4 v = __ldg((const float4*)(X + (size_t)row * M_SZ + c4));
    __half2* dst = (__half2*)(g_AX + ((size_t)(b << 7) + t) * 512 + 256 + c4);
    dst[0] = __floats2half2_rn(v.x, v.y);
    dst[1] = __floats2half2_rn(v.z, v.w);
}

// ---------------- weights -> fp16, fused bias -------------------------------
__global__ void convert_w_kernel(const float* __restrict__ WU_d,
                                 const float* __restrict__ W_hh,
                                 const float* __restrict__ b_ih,
                                 const float* __restrict__ b_hh) {
    int i = blockIdx.x * 256 + threadIdx.x;          // 0 .. 262143
    if (i < 256 * 512) {
        int r = i >> 9, k = i & 511;
        g_Wdd16[i] = __float2half_rn(WU_d[r * 768 + k]);
    }
    if (i < 256 * 256) {
        int r = i >> 8, k = i & 255;
        g_Wdx16[i] = __float2half_rn(WU_d[r * 768 + 512 + k]);
    }
    if (i < 1024 * 256) {
        g_Whh16[i] = __float2half_rn(W_hh[i]);
    }
    if (i < 1024) {
        g_bias[i] = b_ih[i] + b_hh[i];
    }
}

// ---------------- HMMA helpers ----------------------------------------------
__device__ __forceinline__ void ldsm4(uint32_t* r, uint32_t addr) {
    asm volatile("ldmatrix.sync.aligned.m8n8.x4.shared.b16 {%0,%1,%2,%3}, [%4];"
                 : "=r"(r[0]), "=r"(r[1]), "=r"(r[2]), "=r"(r[3]) : "r"(addr));
}

__device__ __forceinline__ void mma_16816(float* acc, const uint32_t* a,
                                          uint32_t b0, uint32_t b1) {
    asm volatile(
        "mma.sync.aligned.m16n8k16.row.col.f32.f16.f16.f32 "
        "{%0,%1,%2,%3},{%4,%5,%6,%7},{%8,%9},{%0,%1,%2,%3};"
        : "+f"(acc[0]), "+f"(acc[1]), "+f"(acc[2]), "+f"(acc[3])
        : "r"(a[0]), "r"(a[1]), "r"(a[2]), "r"(a[3]), "r"(b0), "r"(b1));
}

__device__ __forceinline__ __half2 h2tanh_fast(__half2 x) {
    uint32_t xi = *(uint32_t*)&x, yo;
    asm("tanh.approx.f16x2 %0, %1;" : "=r"(yo) : "r"(xi));
    return *(__half2*)&yo;
}

// 64x64 block tile, 256 threads (8 warps as 2m x 4n, warp tile 32x16).
// K-chunk = 64 halves per stage (nit stages of k=64) -> half the latency chain
// vs k=32. Tile: 64 rows x 72 halves (pad 8) -> conflict-free STS.128 + LDSM.
// PDL=true: weight tile-0 loads issued BEFORE the grid dependency sync.
#define HM_STRIDE 72
#define HM_BUFH   (64 * HM_STRIDE)
template<bool PDL>
__device__ __forceinline__ void hmma_block(
    const __half* __restrict__ Ag0, int lda,
    const __half* __restrict__ Bg0, int ldb,
    int nit, float acc[2][2][4], __half* As, __half* Bs)
{
    const int tid  = threadIdx.x;
    const int lane = tid & 31, warp = tid >> 5;

    // per-thread load slots: rows (tid>>3) and (tid>>3)+32, col (tid&7)*8
    const int lrow = tid >> 3;
    const int lcol = (tid & 7) * 8;
    const __half* Ag = Ag0 + (size_t)lrow * lda + lcol;
    const __half* Bg = Bg0 + (size_t)lrow * ldb + lcol;
    const size_t arow2 = (size_t)32 * lda;
    const size_t brow2 = (size_t)32 * ldb;

    const uint32_t st0 = (uint32_t)(lrow * HM_STRIDE + lcol) * 2;
    const uint32_t st1 = st0 + 32 * HM_STRIDE * 2;
    const uint32_t as_base = (uint32_t)__cvta_generic_to_shared(As);
    const uint32_t bs_base = (uint32_t)__cvta_generic_to_shared(Bs);

    const int arow = (warp >> 2) * 32 + (lane & 7) + ((lane >> 3) & 1) * 8;
    const uint32_t a_off0 = (arow * HM_STRIDE + (lane >> 4) * 8) * 2;
    const uint32_t a_off1 = a_off0 + 16 * HM_STRIDE * 2;
    const int brow = (warp & 3) * 16 + (lane & 7) + (lane >> 4) * 8;
    const uint32_t b_off = (brow * HM_STRIDE + ((lane >> 3) & 1) * 8) * 2;

    // stage 0: weight (B) loads first -- independent of predecessor kernel
    uint4 pb0 = *(const uint4*)Bg;
    uint4 pb1 = *(const uint4*)(Bg + brow2);
    if (PDL) cudaGridDependencySynchronize();
    uint4 pa0 = *(const uint4*)Ag;
    uint4 pa1 = *(const uint4*)(Ag + arow2);

    *(uint4*)((char*)As + st0) = pa0;
    *(uint4*)((char*)As + st1) = pa1;
    *(uint4*)((char*)Bs + st0) = pb0;
    *(uint4*)((char*)Bs + st1) = pb1;
    __syncthreads();

    const uint32_t BUFB = HM_BUFH * 2;
    int buf = 0;
#pragma unroll 1
    for (int it = 0; it < nit; it++) {
        uint4 na0, na1, nb0, nb1;
        const bool more = (it + 1 < nit);
        if (more) {
            const int ko = (it + 1) * 64;
            na0 = *(const uint4*)(Ag + ko);
            na1 = *(const uint4*)(Ag + arow2 + ko);
            nb0 = *(const uint4*)(Bg + ko);
            nb1 = *(const uint4*)(Bg + brow2 + ko);
        }
        const uint32_t ab = as_base + buf * BUFB;
        const uint32_t bb = bs_base + buf * BUFB;
#pragma unroll
        for (int kk = 0; kk < 4; kk++) {
            uint32_t af0[4], af1[4], bf[4];
            ldsm4(af0, ab + a_off0 + kk * 32);
            ldsm4(af1, ab + a_off1 + kk * 32);
            ldsm4(bf,  bb + b_off  + kk * 32);
            mma_16816(acc[0][0], af0, bf[0], bf[1]);
            mma_16816(acc[0][1], af0, bf[2], bf[3]);
            mma_16816(acc[1][0], af1, bf[0], bf[1]);
            mma_16816(acc[1][1], af1, bf[2], bf[3]);
        }
        if (more) {
            const int nb = buf ^ 1;
            *(uint4*)((char*)As + nb * BUFB + st0) = na0;
            *(uint4*)((char*)As + nb * BUFB + st1) = na1;
            *(uint4*)((char*)Bs + nb * BUFB + st0) = nb0;
            *(uint4*)((char*)Bs + nb * BUFB + st1) = nb1;
            __syncthreads();
            buf = nb;
        }
    }
}

// ---------------- per-step GEMMs via HMMA, uniform K=256 tiles ---------------
// grid (16, 24): y 0..3 -> U1 (K 0:256); y 4..7 -> U2 (K 256:512);
//                y 8..23 -> GATES (K=256). Outputs fp16. nit=4 (k=64 chunks).
__global__ void step_gemm_hmma() {
    __shared__ __half As[2][HM_BUFH];
    __shared__ __half Bs[2][HM_BUFH];

    const int y = blockIdx.y;
    const __half* Bg; __half* C; int ldb, ldc, col0, koff;
    if (y < 8) {
        const int half = y >> 2;                 // 0 -> U1, 1 -> U2
        koff = half * 256;
        Bg   = g_Wdd16 + (size_t)(y & 3) * 64 * 512 + koff;
        ldb  = 512; C = half ? g_U2h : g_U1h; ldc = 256; col0 = (y & 3) * 64;
    } else {
        koff = 0;
        Bg   = g_Whh16 + (size_t)(y - 8) * 64 * 256;
        ldb  = 256; C = g_GATESh; ldc = 1024; col0 = (y - 8) * 64;
    }

    float acc[2][2][4] = {};
    hmma_block<true>(g_HCh + (size_t)blockIdx.x * 64 * 512 + koff, 512,
                     Bg, ldb, 4, acc, &As[0][0], &Bs[0][0]);

    const int lane = threadIdx.x & 31, warp = threadIdx.x >> 5;
    const int gid = lane >> 2, tig = lane & 3;
    const int mrow0 = blockIdx.x * 64 + (warp >> 2) * 32;
    const int c0 = col0 + (warp & 3) * 16;
#pragma unroll
    for (int mt = 0; mt < 2; mt++)
#pragma unroll
        for (int nt = 0; nt < 2; nt++) {
            const float* a = acc[mt][nt];
            const int r  = mrow0 + mt * 16 + gid;
            const int cc = c0 + nt * 8 + tig * 2;
            *(__half2*)&C[(size_t)r * ldc + cc]       = __floats2half2_rn(a[0], a[1]);
            *(__half2*)&C[(size_t)(r + 8) * ldc + cc] = __floats2half2_rn(a[2], a[3]);
        }
}

// ---------------- A precompute via HMMA: A half of g_AX ----------------------
__global__ void precompute_A_hmma() {
    __shared__ __half As[2][HM_BUFH];
    __shared__ __half Bs[2][HM_BUFH];

    float acc[2][2][4] = {};
    hmma_block<false>(g_AX + (size_t)blockIdx.x * 64 * 512 + 256, 512,
                      g_Wdx16 + (size_t)blockIdx.y * 64 * 256, 256, 4,
                      acc, &As[0][0], &Bs[0][0]);

    const int lane = threadIdx.x & 31, warp = threadIdx.x >> 5;
    const int gid = lane >> 2, tig = lane & 3;
    const int mrow0 = blockIdx.x * 64 + (warp >> 2) * 32;
    const int c0 = blockIdx.y * 64 + (warp & 3) * 16;
#pragma unroll
    for (int mt = 0; mt < 2; mt++)
#pragma unroll
        for (int nt = 0; nt < 2; nt++) {
            const float* a = acc[mt][nt];
            const int r  = mrow0 + mt * 16 + gid;
            const int cc = c0 + nt * 8 + tig * 2;
            *(__half2*)&g_AX[(size_t)r * 512 + cc]       = __floats2half2_rn(a[0], a[1]);
            *(__half2*)&g_AX[(size_t)(r + 8) * 512 + cc] = __floats2half2_rn(a[2], a[3]);
        }
}

// ---------------- fused attention (online softmax) + LSTM step --------------
// 512 blocks, 2 batches per block; warps 0-3 -> batch0, warps 4-7 -> batch1.
// Serpentine t-sweep (L2-resident re-reads); PDL prefetch + early trigger.
__global__ void __launch_bounds__(256, 4)
attn_lstm_kernel(const float* __restrict__ v_d,
                 const float* __restrict__ Wl,
                 const float* __restrict__ Y,
                 const float* __restrict__ W_ih,
                 int t_step)
{
    __shared__ float ctx_ws[8][M_SZ];
    __shared__ float wM[8], wS[8];
    __shared__ float redy[2][8];
    __shared__ float yt_s[2];

    const int tid  = threadIdx.x;     // 0..255
    const int lane = tid & 31;
    const int warp = tid >> 5;
    const int wg   = warp & 3;        // t offset within batch
    const int bg   = warp >> 2;       // which batch of the pair
    const int b    = blockIdx.x * 2 + bg;

    // serpentine direction
    const int dir   = t_step & 1;
    const int r0    = dir ? (T_SZ - 1 - wg) : wg;
    const int rstep = dir ? -4 : 4;

    // ---- prologue independent of predecessor: AX pipeline warm-up + v_d ----
    const float4* AXrow = (const float4*)(g_AX + (size_t)b * T_SZ * 512) + lane;
    float4 a0 = __ldg(AXrow + (size_t)r0 * 64);
    float4 x0 = __ldg(AXrow + (size_t)r0 * 64 + 32);
    float4 a1 = __ldg(AXrow + (size_t)(r0 + rstep) * 64);
    float4 x1 = __ldg(AXrow + (size_t)(r0 + rstep) * 64 + 32);
    const int mb = lane * 8;
    float4 va  = __ldg((const float4*)(v_d + mb));
    float4 vb  = __ldg((const float4*)(v_d + mb + 4));

    // ---- wait for step_gemm's U/GATES ----
    cudaGridDependencySynchronize();

    // per-lane u,v slices as half2 (m = lane*8 .. lane*8+7), reused 32x
    __half2 u2[4], v2[4];
    {
        uint4 u1r = __ldg((const uint4*)(g_U1h + b * M_SZ) + lane);
        uint4 u2r = __ldg((const uint4*)(g_U2h + b * M_SZ) + lane);
        const __half2* p1 = (const __half2*)&u1r;
        const __half2* p2 = (const __half2*)&u2r;
#pragma unroll
        for (int j = 0; j < 4; j++) u2[j] = __hadd2(p1[j], p2[j]);
        v2[0] = __floats2half2_rn(va.x, va.y);
        v2[1] = __floats2half2_rn(va.z, va.w);
        v2[2] = __floats2half2_rn(vb.x, vb.y);
        v2[3] = __floats2half2_rn(vb.z, vb.w);
    }

    // single pass: logits + online softmax + ctx accumulation
    float C[8] = {0, 0, 0, 0, 0, 0, 0, 0};
    float Mx = -1e30f, S = 0.0f;

#pragma unroll 4
    for (int i = 0; i < 32; i++) {
        float4 a2, x2;
        if (i < 30) {
            const int rn = r0 + (i + 2) * rstep;
            a2 = __ldg(AXrow + (size_t)rn * 64);
            x2 = __ldg(AXrow + (size_t)rn * 64 + 32);
        }

        // logit partial from this lane's 8 m-values (f16x2 path)
        const __half2* ahp = (const __half2*)&a0;
        const __half2* xhp = (const __half2*)&x0;
        __half2 acch = __floats2half2_rn(0.0f, 0.0f);
        float xv[8];
#pragma unroll
        for (int j = 0; j < 4; j++) {
            __half2 s  = __hadd2(u2[j], ahp[j]);
            __half2 th = h2tanh_fast(s);
            acch = __hfma2(v2[j], th, acch);
            float2 xf = __half22float2(xhp[j]);
            xv[2 * j] = xf.x; xv[2 * j + 1] = xf.y;
        }
        float acc = __low2float(acch) + __high2float(acch);
#pragma unroll
        for (int o = 16; o; o >>= 1) acc += __shfl_xor_sync(0xffffffffu, acc, o);
        // acc = l_t, uniform across warp

        if (acc <= Mx) {                 // warp-uniform branch
            float e = __expf(acc - Mx);
            S += e;
#pragma unroll
            for (int j = 0; j < 8; j++) C[j] = fmaf(e, xv[j], C[j]);
        } else {
            float f = __expf(Mx - acc);
            S = fmaf(S, f, 1.0f);
#pragma unroll
            for (int j = 0; j < 8; j++) C[j] = fmaf(C[j], f, xv[j]);
            Mx = acc;
        }

        a0 = a1; x0 = x1; a1 = a2; x1 = x2;
    }

    // per-warp results -> smem
    if (lane == 0) { wM[warp] = Mx; wS[warp] = S; }
    *(float4*)&ctx_ws[warp][lane * 8]     = make_float4(C[0], C[1], C[2], C[3]);
    *(float4*)&ctx_ws[warp][lane * 8 + 4] = make_float4(C[4], C[5], C[6], C[7]);
    __syncthreads();

    // per-batch combine (each thread computes ctx[m=tid] for both batches)
    float cg[2];
#pragma unroll
    for (int g = 0; g < 2; g++) {
        float Mg = fmaxf(fmaxf(wM[4 * g], wM[4 * g + 1]),
                         fmaxf(wM[4 * g + 2], wM[4 * g + 3]));
        float Sg = 0.0f, c = 0.0f;
#pragma unroll
        for (int w = 0; w < 4; w++) {
            float f = __expf(wM[4 * g + w] - Mg);
            Sg = fmaf(wS[4 * g + w], f, Sg);
            c  = fmaf(f, ctx_ws[4 * g + w][tid], c);
        }
        cg[g] = c / Sg;
    }

    if (t_step == TS - 1) {
        g_CTX[(blockIdx.x * 2)     * M_SZ + tid] = cg[0];
        g_CTX[(blockIdx.x * 2 + 1) * M_SZ + tid] = cg[1];
    }

    // y_tilde per batch: Wl[0]*y_t + sum_m Wl[1+m]*ctx[m]
    const float wl = __ldg(Wl + 1 + tid);
#pragma unroll
    for (int g = 0; g < 2; g++) {
        float yv = wl * cg[g];
#pragma unroll
        for (int o = 16; o; o >>= 1) yv += __shfl_xor_sync(0xffffffffu, yv, o);
        if (lane == 0) redy[g][warp] = yv;
    }
    __syncthreads();
    if (tid < 2) {
        float s = redy[tid][0] + redy[tid][1] + redy[tid][2] + redy[tid][3]
                + redy[tid][4] + redy[tid][5] + redy[tid][6] + redy[tid][7];
        yt_s[tid] = fmaf(__ldg(Wl),
                         Y[(size_t)(blockIdx.x * 2 + tid) * TS + t_step], s);
    }
    __syncthreads();

    // fused LSTM pointwise update for both batches
    const int p = tid;
    const float wi0 = __ldg(W_ih + p);
    const float wi1 = __ldg(W_ih + P_SZ + p);
    const float wi2 = __ldg(W_ih + 2 * P_SZ + p);
    const float wi3 = __ldg(W_ih + 3 * P_SZ + p);
    const float bz0 = g_bias[p], bz1 = g_bias[P_SZ + p];
    const float bz2 = g_bias[2 * P_SZ + p], bz3 = g_bias[3 * P_SZ + p];

#pragma unroll
    for (int g = 0; g < 2; g++) {
        const int bb = blockIdx.x * 2 + g;
        const float yt = yt_s[g];
        const __half* gr = g_GATESh + (size_t)bb * 4 * P_SZ;
        float ig = __half2float(gr[p])            + yt * wi0 + bz0;
        float fg = __half2float(gr[P_SZ + p])     + yt * wi1 + bz1;
        float gg = __half2float(gr[2 * P_SZ + p]) + yt * wi2 + bz2;
        float og = __half2float(gr[3 * P_SZ + p]) + yt * wi3 + bz3;

        float cold = g_HC[(size_t)bb * 512 + 256 + p];
        float si = 1.0f / (1.0f + __expf(-ig));
        float sf = 1.0f / (1.0f + __expf(-fg));
        float so = 1.0f / (1.0f + __expf(-og));
        float cn = sf * cold + si * tanhf(gg);
        float hn = so * tanhf(cn);

        g_HC[(size_t)bb * 512 + p]        = hn;
        g_HC[(size_t)bb * 512 + 256 + p]  = cn;
        g_HCh[(size_t)bb * 512 + p]       = __float2half_rn(hn);
        g_HCh[(size_t)bb * 512 + 256 + p] = __float2half_rn(cn);
    }

    // make h,c visible, then let the next step's GEMM launch
    __threadfence();
    __syncthreads();
    cudaTriggerProgrammaticLaunchCompletion();
}

// ---------------- final head: out = ([h,ctx] @ Wb^T + b) @ vb^T + vb_b -----
__global__ void final_head_kernel(const float* __restrict__ Wb_w,
                                  const float* __restrict__ Wb_b,
                                  const float* __restrict__ vb_w,
                                  const float* __restrict__ vb_b,
                                  float* __restrict__ out)
{
    const int b   = blockIdx.x;
    const int tid = threadIdx.x;  // 0..255 = p
    __shared__ float hc_s[512];
    __shared__ float red[8];

    hc_s[tid]        = g_HC[(size_t)b * 512 + tid];        // h
    hc_s[P_SZ + tid] = g_CTX[(size_t)b * M_SZ + tid];      // ctx
    __syncthreads();

    const float* wr = Wb_w + (size_t)tid * (P_SZ + M_SZ);
    float t = __ldg(Wb_b + tid);
#pragma unroll 4
    for (int k = 0; k < 2 * P_SZ; k++)
        t = fmaf(__ldg(wr + k), hc_s[k], t);
    float val = __ldg(vb_w + tid) * t;

    int lane = tid & 31, warp = tid >> 5;
#pragma unroll
    for (int o = 16; o; o >>= 1) val += __shfl_xor_sync(0xffffffffu, val, o);
    if (lane == 0) red[warp] = val;
    __syncthreads();
    if (tid == 0)
        out[b] = vb_b[0] + red[0] + red[1] + red[2] + red[3]
                         + red[4] + red[5] + red[6] + red[7];
}

// ---------------- launch ----------------------------------------------------
extern "C" void kernel_launch(void* const* d_in, const int* in_sizes, int n_in,
                              void* d_out, int out_size)
{
    const float* Y    = (const float*)d_in[0];
    const float* X    = (const float*)d_in[1];
    const float* WU_d = (const float*)d_in[2];
    const float* v_d  = (const float*)d_in[3];
    const float* Wl   = (const float*)d_in[4];
    const float* W_ih = (const float*)d_in[5];
    const float* W_hh = (const float*)d_in[6];
    const float* b_ih = (const float*)d_in[7];
    const float* b_hh = (const float*)d_in[8];
    const float* Wb_w = (const float*)d_in[9];
    const float* Wb_b = (const float*)d_in[10];
    const float* vb_w = (const float*)d_in[11];
    const float* vb_b = (const float*)d_in[12];
    float* out = (float*)d_out;

    // init h, c = 0 (fp32 + fp16 mirrors)
    init_hc_kernel<<<(B_SZ * 512 + 255) / 256, 256>>>();

    // X -> interleaved AX (X half) fp16 ; weights -> fp16 ; fused bias
    convert_x_kernel<<<(T_SZ * B_SZ) / 4, 256>>>(X);
    convert_w_kernel<<<1024, 256>>>(WU_d, W_hh, b_ih, b_hh);

    // A half of g_AX = X16 @ Wdx^T (HMMA)
    precompute_A_hmma<<<dim3((B_SZ * T_SZ) / 64, M_SZ / 64), 256>>>();

    // PDL-chained recurrence
    cudaLaunchAttribute pdl[1];
    pdl[0].id = cudaLaunchAttributeProgrammaticStreamSerialization;
    pdl[0].val.programmaticStreamSerializationAllowed = 1;

    cudaLaunchConfig_t cfg_g = {};
    cfg_g.gridDim  = dim3(B_SZ / 64, 24);
    cfg_g.blockDim = dim3(256);
    cfg_g.stream   = 0;
    cfg_g.attrs    = pdl;
    cfg_g.numAttrs = 1;

    cudaLaunchConfig_t cfg_a = {};
    cfg_a.gridDim  = dim3(B_SZ / 2);
    cfg_a.blockDim = dim3(256);
    cfg_a.stream   = 0;
    cfg_a.attrs    = pdl;
    cfg_a.numAttrs = 1;

    for (int t = 0; t < TS; t++) {
        cudaLaunchKernelEx(&cfg_g, step_gemm_hmma);
        cudaLaunchKernelEx(&cfg_a, attn_lstm_kernel, v_d, Wl, Y, W_ih, t);
    }

    final_head_kernel<<<B_SZ, 256>>>(Wb_w, Wb_b, vb_w, vb_b, out);
}